// round 9
// baseline (speedup 1.0000x reference)
#include <cuda_runtime.h>
#include <math.h>

typedef unsigned long long ull;
typedef unsigned int uint32;

// LureSystem on GB300 — R8: two independent 320-thread pipelines per CTA
// (batch-split), named barriers + cluster-scope mbarriers, so one half's
// exchange/barrier latency is hidden behind the other half's compute.
// 16 groups x 8-CTA clusters; rank owns 32 w/x rows + 8 fused-e rows.

#define NSTEPS 2048
#define RANKS 8
#define GROUPS 16
#define THREADS 640
#define HALF_T 320

#define S_ACT 584
#define PARW 288            // w-phase per-chunk partials (8 batches x 36)
#define PARX 352            // xe-phase per-chunk partials (8 batches x 44)
#define PAR_HALF 5760       // max(20*288, 16*352)

// SMEM float offsets
#define OFF_W1T 0           // [320][32]  [C2|D21]^T rows rw..rw+31
#define OFF_W2T 10240       // [576][40]  rows 0-31 [A|B|B2]^T, 32-39 fused E^T
#define OFF_ACT 33280       // 2 x [8][584]
#define OFF_PAR 42624       // 2 x 5760
#define SMEM_FLOATS 54144   // 216576 bytes

#define E_SIZE (256 * NSTEPS * 64)
#define BASE_X E_SIZE
#define BASE_W (E_SIZE + 256 * 256)

__device__ float g_EW[64 * 576];
__device__ float g_wbuf[GROUPS * 2 * 8 * 256];   // [group][half][batch][256]
__device__ float g_xbuf[GROUPS * 2 * 8 * 256];

__device__ __forceinline__ uint32 smem_u32(const void* p) {
    uint32 a;
    asm("{ .reg .u64 tmp; cvta.to.shared.u64 tmp, %1; cvt.u32.u64 %0, tmp; }"
        : "=r"(a) : "l"(p));
    return a;
}

__device__ __forceinline__ void mbar_init(uint32 mbar, uint32 cnt) {
    asm volatile("mbarrier.init.shared.b64 [%0], %1;" :: "r"(mbar), "r"(cnt) : "memory");
}
// release at cluster scope: orders prior (CTA-barrier-collected) st.cg for peers
__device__ __forceinline__ void mbar_arrive_peer(uint32 mbar, uint32 rank) {
    asm volatile(
        "{\n\t.reg .b32 ra;\n\t"
        "mapa.shared::cluster.u32 ra, %0, %1;\n\t"
        "mbarrier.arrive.release.cluster.shared::cluster.b64 _, [ra];\n\t}"
        :: "r"(mbar), "r"(rank) : "memory");
}
__device__ __forceinline__ void mbar_wait(uint32 mbar, uint32 parity) {
    asm volatile(
        "{\n\t.reg .pred P;\n\t"
        "W%=:\n\t"
        "mbarrier.try_wait.parity.acquire.cluster.shared::cta.b64 P, [%0], %1, 0x989680;\n\t"
        "@P bra.uni D%=;\n\t"
        "bra.uni W%=;\n\t"
        "D%=:\n\t}"
        :: "r"(mbar), "r"(parity) : "memory");
}
__device__ __forceinline__ void bar_half(int half) {
    asm volatile("bar.sync %0, %1;" :: "r"(1 + half), "r"(HALF_T) : "memory");
}

__device__ __forceinline__ void fma2(ull& acc, ull m, ull a) {
    asm("fma.rn.f32x2 %0, %1, %2, %0;" : "+l"(acc) : "l"(m), "l"(a));
}
__device__ __forceinline__ ull pack2(float x) {
    ull r; asm("mov.b64 %0, {%1, %1};" : "=l"(r) : "f"(x)); return r;
}

// 4 rows x 4 batches (b = b0 + 2*kk) over K-chunk of 4*L4, f32x2 FMAs.
// WS = weight stride, PS = partials batch stride.
template <int L4, int WS, int PS>
__device__ __forceinline__ void mmT(const float* __restrict__ WT,
                                    const float* __restrict__ Act,
                                    float* __restrict__ P) {
    ull a01[4] = {0ull, 0ull, 0ull, 0ull};
    ull a23[4] = {0ull, 0ull, 0ull, 0ull};
#pragma unroll
    for (int j4 = 0; j4 < L4; j4++) {
        float av[4][4];
#pragma unroll
        for (int kk = 0; kk < 4; kk++) {
            float4 t4 = *reinterpret_cast<const float4*>(Act + kk * (2 * S_ACT) + 4 * j4);
            av[kk][0] = t4.x; av[kk][1] = t4.y; av[kk][2] = t4.z; av[kk][3] = t4.w;
        }
#pragma unroll
        for (int jj = 0; jj < 4; jj++) {
            ulonglong2 m = *reinterpret_cast<const ulonglong2*>(WT + (4 * j4 + jj) * WS);
#pragma unroll
            for (int kk = 0; kk < 4; kk++) {
                ull aa = pack2(av[kk][jj]);
                fma2(a01[kk], m.x, aa);
                fma2(a23[kk], m.y, aa);
            }
        }
    }
#pragma unroll
    for (int kk = 0; kk < 4; kk++)
        *reinterpret_cast<ulonglong2*>(P + kk * (2 * PS)) = make_ulonglong2(a01[kk], a23[kk]);
}

// ---- pre-kernel: fused e-weights EW = [C@A | C@B + D | C@B2 + D12] ----
__global__ void fuse_kernel(const float* __restrict__ A, const float* __restrict__ B,
                            const float* __restrict__ B2, const float* __restrict__ C,
                            const float* __restrict__ D, const float* __restrict__ D12) {
    __shared__ float c[256];
    int i = blockIdx.x;
    for (int idx = threadIdx.x; idx < 256; idx += blockDim.x) c[idx] = C[i * 256 + idx];
    __syncthreads();
    for (int j = threadIdx.x; j < 576; j += blockDim.x) {
        float s = 0.f;
        if (j < 256) {
            for (int kk = 0; kk < 256; kk++) s = fmaf(c[kk], A[kk * 256 + j], s);
        } else if (j < 320) {
            int jj = j - 256;
            for (int kk = 0; kk < 256; kk++) s = fmaf(c[kk], B[kk * 64 + jj], s);
            s += D[i * 64 + jj];
        } else {
            int jj = j - 320;
            for (int kk = 0; kk < 256; kk++) s = fmaf(c[kk], B2[kk * 256 + jj], s);
            s += D12[i * 256 + jj];
        }
        g_EW[i * 576 + j] = s;
    }
}

__global__ void __cluster_dims__(RANKS, 1, 1) __launch_bounds__(THREADS, 1)
lure_kernel(const float* __restrict__ dseq,
            const float* __restrict__ x0,
            const float* __restrict__ Amat,
            const float* __restrict__ Bmat,
            const float* __restrict__ B2mat,
            const float* __restrict__ C2mat,
            const float* __restrict__ D21mat,
            float* __restrict__ out) {
    extern __shared__ float smem[];
    __shared__ ull s_mbar[4];   // [half][phase: w=0,x=1]

    float* sW1T = smem + OFF_W1T;
    float* sW2T = smem + OFF_W2T;

    const int t = threadIdx.x;
    const int g = blockIdx.x >> 3;
    const int r = blockIdx.x & 7;
    const int rw = r * 32;
    const int re = r * 8;

    // ---- resident weights (transposed [K][row]) ----
    for (int idx = t; idx < 320 * 32; idx += THREADS) {
        int row = idx & 31, j = idx >> 5;
        float v = (j < 256) ? C2mat[(rw + row) * 256 + j]
                            : D21mat[(rw + row) * 64 + (j - 256)];
        sW1T[j * 32 + row] = v;
    }
    for (int idx = t; idx < 576 * 40; idx += THREADS) {
        int row = idx % 40, j = idx / 40;
        float v;
        if (row < 32) {
            int gr = rw + row;
            if (j < 256)      v = Amat[gr * 256 + j];
            else if (j < 320) v = Bmat[gr * 64 + (j - 256)];
            else              v = B2mat[gr * 256 + (j - 320)];
        } else {
            v = g_EW[(re + row - 32) * 576 + j];
        }
        sW2T[j * 40 + row] = v;
    }
    // x0 + d_0 for both halves
    for (int idx = t; idx < 16 * 256; idx += THREADS) {
        int b = idx >> 8, col = idx & 255;          // b 0..15 across halves
        smem[OFF_ACT + (b >> 3) * (8 * S_ACT) + (b & 7) * S_ACT + col] =
            x0[(g * 16 + b) * 256 + col];
    }
    for (int idx = t; idx < 16 * 64; idx += THREADS) {
        int b = idx >> 6, j = idx & 63;
        smem[OFF_ACT + (b >> 3) * (8 * S_ACT) + (b & 7) * S_ACT + 256 + j] =
            dseq[(size_t)(g * 16 + b) * (NSTEPS * 64) + j];
    }
    if (t == 0) {
        for (int i = 0; i < 4; i++) mbar_init(smem_u32(&s_mbar[i]), RANKS);
    }
    __syncthreads();
    asm volatile("barrier.cluster.arrive.aligned;" ::: "memory");
    asm volatile("barrier.cluster.wait.aligned;" ::: "memory");

    // ---- per-half decomposition ----
    const int half = t / HALF_T;
    const int t2 = t - half * HALF_T;
    float* sA  = smem + OFF_ACT + half * (8 * S_ACT);
    float* sP  = smem + OFF_PAR + half * PAR_HALF;
    const uint32 mb_w = smem_u32(&s_mbar[half * 2 + 0]);
    const uint32 mb_x = smem_u32(&s_mbar[half * 2 + 1]);

    const int cw = t2 >> 4, tw = t2 & 15;               // w: 20 chunks x 16 tiles
    const int row0w = (tw & 7) * 4, b0w = tw >> 3;
    const int j0w = cw * 16;
    const int cx = t2 / 20, tx = t2 % 20;               // xe: 16 chunks x 20 tiles
    const int row0x = (tx % 10) * 4, b0x = tx / 10;
    const int j0x = cx * 36;
    const int rb = t2 >> 5, rr = t2 & 31;               // w reduce (t2<256)
    const int xb = t2 / 40, xr = t2 % 40;               // xe reduce (all 320)

    float* gw = g_wbuf + (g * 2 + half) * (8 * 256);
    float* gx = g_xbuf + (g * 2 + half) * (8 * 256);
    const float* dbase = dseq + (size_t)(g * 16 + half * 8) * (NSTEPS * 64);
    float* outE = out + (size_t)(g * 16 + half * 8) * (NSTEPS * 64);

    float dpre0 = 0.f, dpre1 = 0.f;
    const int d0b = t2 >> 6, d0j = t2 & 63;             // idx t2 (<320)
    const int i1 = t2 + HALF_T;
    const int d1b = i1 >> 6, d1j = i1 & 63;             // idx t2+320 (<512)

    for (int k = 0; k < NSTEPS; ++k) {
        const uint32 par = k & 1;

        // ---- w-phase mm: 32 rows, K=320 ----
        mmT<4, 32, 36>(sW1T + j0w * 32 + row0w,
                       sA + b0w * S_ACT + j0w,
                       sP + cw * PARW + b0w * 36 + row0w);
        bar_half(half);
        if (t2 < 256) {
            float s = 0.f;
#pragma unroll
            for (int c = 0; c < 20; c++) s += sP[c * PARW + rb * 36 + rr];
            __stcg(&gw[rb * 256 + rw + rr], tanhf(s));
        }
        bar_half(half);
        if (t2 == 0) {
#pragma unroll
            for (int p = 0; p < RANKS; p++) mbar_arrive_peer(mb_w, p);
        }
        // overlap mbar latency: prefetch d_{k+1}
        {
            int kp = (k + 1 < NSTEPS) ? (k + 1) : (NSTEPS - 1);
            dpre0 = dbase[(size_t)d0b * (NSTEPS * 64) + (size_t)kp * 64 + d0j];
            if (i1 < 512)
                dpre1 = dbase[(size_t)d1b * (NSTEPS * 64) + (size_t)kp * 64 + d1j];
        }
        mbar_wait(mb_w, par);
        // gather full w (2048 floats) as float4
        {
            int v = t2;
            float4 q = *(const float4*)__builtin_assume_aligned(
                (const void*)&gw[(v >> 6) * 256 + (v & 63) * 4], 16);
            *reinterpret_cast<float4*>(&sA[(v >> 6) * S_ACT + 320 + (v & 63) * 4]) =
                make_float4(__ldcg(&gw[(v >> 6) * 256 + (v & 63) * 4 + 0]),
                            __ldcg(&gw[(v >> 6) * 256 + (v & 63) * 4 + 1]),
                            __ldcg(&gw[(v >> 6) * 256 + (v & 63) * 4 + 2]),
                            __ldcg(&gw[(v >> 6) * 256 + (v & 63) * 4 + 3]));
            (void)q;
            v = t2 + HALF_T;
            if (v < 512) {
                *reinterpret_cast<float4*>(&sA[(v >> 6) * S_ACT + 320 + (v & 63) * 4]) =
                    make_float4(__ldcg(&gw[(v >> 6) * 256 + (v & 63) * 4 + 0]),
                                __ldcg(&gw[(v >> 6) * 256 + (v & 63) * 4 + 1]),
                                __ldcg(&gw[(v >> 6) * 256 + (v & 63) * 4 + 2]),
                                __ldcg(&gw[(v >> 6) * 256 + (v & 63) * 4 + 3]));
            }
        }
        bar_half(half);

        // ---- xe-phase mm: 40 rows (32 x' + 8 e), K=576 ----
        mmT<9, 40, 44>(sW2T + j0x * 40 + row0x,
                       sA + b0x * S_ACT + j0x,
                       sP + cx * PARX + b0x * 44 + row0x);
        bar_half(half);
        float xres = 0.f;
        {
#pragma unroll
            for (int c = 0; c < 16; c++) xres += sP[c * PARX + xb * 44 + xr];
            if (xr < 32) __stcg(&gx[xb * 256 + rw + xr], xres);
        }
        bar_half(half);
        if (t2 == 0) {
#pragma unroll
            for (int p = 0; p < RANKS; p++) mbar_arrive_peer(mb_x, p);
        }
        // overlap mbar latency: e outputs + d commit
        if (xr >= 32)
            outE[(size_t)xb * (NSTEPS * 64) + (size_t)k * 64 + re + (xr - 32)] = xres;
        sA[d0b * S_ACT + 256 + d0j] = dpre0;
        if (i1 < 512) sA[d1b * S_ACT + 256 + d1j] = dpre1;
        mbar_wait(mb_x, par);
        // gather full x_new (2048 floats)
        {
            int v = t2;
            *reinterpret_cast<float4*>(&sA[(v >> 6) * S_ACT + (v & 63) * 4]) =
                make_float4(__ldcg(&gx[(v >> 6) * 256 + (v & 63) * 4 + 0]),
                            __ldcg(&gx[(v >> 6) * 256 + (v & 63) * 4 + 1]),
                            __ldcg(&gx[(v >> 6) * 256 + (v & 63) * 4 + 2]),
                            __ldcg(&gx[(v >> 6) * 256 + (v & 63) * 4 + 3]));
            v = t2 + HALF_T;
            if (v < 512) {
                *reinterpret_cast<float4*>(&sA[(v >> 6) * S_ACT + (v & 63) * 4]) =
                    make_float4(__ldcg(&gx[(v >> 6) * 256 + (v & 63) * 4 + 0]),
                                __ldcg(&gx[(v >> 6) * 256 + (v & 63) * 4 + 1]),
                                __ldcg(&gx[(v >> 6) * 256 + (v & 63) * 4 + 2]),
                                __ldcg(&gx[(v >> 6) * 256 + (v & 63) * 4 + 3]));
            }
        }
        bar_half(half);
    }

    // final states from this half's act buffer
    if (t2 < 256) {
        int b = t2 >> 5, row = t2 & 31;
        size_t gb = (size_t)(g * 16 + half * 8 + b);
        out[BASE_X + gb * 256 + rw + row] = sA[b * S_ACT + rw + row];
        out[BASE_W + gb * 256 + rw + row] = sA[b * S_ACT + 320 + rw + row];
    }
}

extern "C" void kernel_launch(void* const* d_in, const int* in_sizes, int n_in,
                              void* d_out, int out_size) {
    (void)in_sizes; (void)n_in; (void)out_size;
    const float* dseq = (const float*)d_in[0];
    const float* x0   = (const float*)d_in[1];
    const float* A    = (const float*)d_in[2];
    const float* B    = (const float*)d_in[3];
    const float* B2   = (const float*)d_in[4];
    const float* C    = (const float*)d_in[5];
    const float* D    = (const float*)d_in[6];
    const float* D12  = (const float*)d_in[7];
    const float* C2   = (const float*)d_in[8];
    const float* D21  = (const float*)d_in[9];
    float* out = (float*)d_out;

    fuse_kernel<<<64, 256>>>(A, B, B2, C, D, D12);

    const size_t smem_bytes = (size_t)SMEM_FLOATS * sizeof(float);
    cudaFuncSetAttribute(lure_kernel, cudaFuncAttributeMaxDynamicSharedMemorySize,
                         (int)smem_bytes);
    lure_kernel<<<GROUPS * RANKS, THREADS, smem_bytes>>>(dseq, x0, A, B, B2,
                                                         C2, D21, out);
}

// round 12
// speedup vs baseline: 2.4152x; 2.4152x over previous
#include <cuda_runtime.h>
#include <math.h>

typedef unsigned long long ull;

// LureSystem on GB300 — R10. R9 (split cluster arrive/wait + xe K-split in the
// exchange window) with the exchange-gather fixed: 1024 float4 per exchange
// (512 threads x 2), previously only 512 (stale batches 8-15).
// 16 groups x 8-CTA clusters, 640 threads.

#define NSTEPS 2048
#define RANKS 8
#define GROUPS 16
#define BT 16
#define THREADS 640

#define S_ACT 584           // [x(256)|d(64)|w(256)]; %32==8
#define PS_W 40             // w partials batch stride
#define PARW 640            // w per-chunk stride = 16*40
#define PS_X 44             // xe partials batch stride
#define PARX 712            // xe per-chunk stride = 16*44 + 8 (bank stagger)

// SMEM float offsets
#define OFF_W1T 0           // [320][32]  [C2|D21]^T rows rw..rw+31
#define OFF_W2T 10240       // [576][40]  rows 0-31 [A|B|B2]^T, 32-39 fused E^T
#define OFF_ACT 33280       // [16][584]
#define OFF_PAR 42624       // max(20*640, 16*712) = 12800
#define SMEM_FLOATS 55424   // 221696 bytes

#define E_SIZE (256 * NSTEPS * 64)
#define BASE_X E_SIZE
#define BASE_W (E_SIZE + 256 * 256)

__device__ float g_EW[64 * 576];
__device__ float g_wbuf[GROUPS * BT * 256];
__device__ float g_xbuf[GROUPS * BT * 256];

__device__ __forceinline__ void cluster_arrive() {
    asm volatile("barrier.cluster.arrive.aligned;" ::: "memory");
}
__device__ __forceinline__ void cluster_wait() {
    asm volatile("barrier.cluster.wait.aligned;" ::: "memory");
}

__device__ __forceinline__ void fma2(ull& acc, ull m, ull a) {
    asm("fma.rn.f32x2 %0, %1, %2, %0;" : "+l"(acc) : "l"(m), "l"(a));
}
__device__ __forceinline__ ull pack2(float x) {
    ull r; asm("mov.b64 %0, {%1, %1};" : "=l"(r) : "f"(x)); return r;
}

// 4 rows x 4 batches (b = b0 + 4*kk) over K-chunk of 4*L4 with weight
// double-buffering. Accumulators persist across calls (passed by reference).
template <int L4, int WS>
__device__ __forceinline__ void mmT(const float* __restrict__ WT,
                                    const float* __restrict__ Act,
                                    ull (&a01)[4], ull (&a23)[4]) {
    ulonglong2 wv[2][4];
#pragma unroll
    for (int jj = 0; jj < 4; jj++)
        wv[0][jj] = *reinterpret_cast<const ulonglong2*>(WT + jj * WS);
#pragma unroll
    for (int j4 = 0; j4 < L4; j4++) {
        const int cur = j4 & 1, nxt = cur ^ 1;
        if (j4 + 1 < L4) {
#pragma unroll
            for (int jj = 0; jj < 4; jj++)
                wv[nxt][jj] = *reinterpret_cast<const ulonglong2*>(
                    WT + (4 * (j4 + 1) + jj) * WS);
        }
        float av[4][4];
#pragma unroll
        for (int kk = 0; kk < 4; kk++) {
            float4 t4 = *reinterpret_cast<const float4*>(Act + kk * (4 * S_ACT) + 4 * j4);
            av[kk][0] = t4.x; av[kk][1] = t4.y; av[kk][2] = t4.z; av[kk][3] = t4.w;
        }
#pragma unroll
        for (int jj = 0; jj < 4; jj++) {
#pragma unroll
            for (int kk = 0; kk < 4; kk++) {
                ull aa = pack2(av[kk][jj]);
                fma2(a01[kk], wv[cur][jj].x, aa);
                fma2(a23[kk], wv[cur][jj].y, aa);
            }
        }
    }
}

// ---- pre-kernel: fused e-weights EW = [C@A | C@B + D | C@B2 + D12] ----
__global__ void fuse_kernel(const float* __restrict__ A, const float* __restrict__ B,
                            const float* __restrict__ B2, const float* __restrict__ C,
                            const float* __restrict__ D, const float* __restrict__ D12) {
    __shared__ float c[256];
    int i = blockIdx.x;
    for (int idx = threadIdx.x; idx < 256; idx += blockDim.x) c[idx] = C[i * 256 + idx];
    __syncthreads();
    for (int j = threadIdx.x; j < 576; j += blockDim.x) {
        float s = 0.f;
        if (j < 256) {
            for (int kk = 0; kk < 256; kk++) s = fmaf(c[kk], A[kk * 256 + j], s);
        } else if (j < 320) {
            int jj = j - 256;
            for (int kk = 0; kk < 256; kk++) s = fmaf(c[kk], B[kk * 64 + jj], s);
            s += D[i * 64 + jj];
        } else {
            int jj = j - 320;
            for (int kk = 0; kk < 256; kk++) s = fmaf(c[kk], B2[kk * 256 + jj], s);
            s += D12[i * 256 + jj];
        }
        g_EW[i * 576 + j] = s;
    }
}

__global__ void __cluster_dims__(RANKS, 1, 1) __launch_bounds__(THREADS, 1)
lure_kernel(const float* __restrict__ dseq,
            const float* __restrict__ x0,
            const float* __restrict__ Amat,
            const float* __restrict__ Bmat,
            const float* __restrict__ B2mat,
            const float* __restrict__ C2mat,
            const float* __restrict__ D21mat,
            float* __restrict__ out) {
    extern __shared__ float smem[];
    float* sW1T = smem + OFF_W1T;
    float* sW2T = smem + OFF_W2T;
    float* sAct = smem + OFF_ACT;
    float* sPar = smem + OFF_PAR;

    const int t = threadIdx.x;
    const int g = blockIdx.x >> 3;
    const int r = blockIdx.x & 7;
    const int rw = r * 32;
    const int re = r * 8;

    // ---- resident weights (transposed [K][row]) ----
    for (int idx = t; idx < 320 * 32; idx += THREADS) {
        int row = idx & 31, j = idx >> 5;
        float v = (j < 256) ? C2mat[(rw + row) * 256 + j]
                            : D21mat[(rw + row) * 64 + (j - 256)];
        sW1T[j * 32 + row] = v;
    }
    for (int idx = t; idx < 576 * 40; idx += THREADS) {
        int row = idx % 40, j = idx / 40;
        float v;
        if (row < 32) {
            int gr = rw + row;
            if (j < 256)      v = Amat[gr * 256 + j];
            else if (j < 320) v = Bmat[gr * 64 + (j - 256)];
            else              v = B2mat[gr * 256 + (j - 320)];
        } else {
            v = g_EW[(re + row - 32) * 576 + j];
        }
        sW2T[j * 40 + row] = v;
    }
    for (int idx = t; idx < BT * 256; idx += THREADS) {
        int b = idx >> 8, col = idx & 255;
        sAct[b * S_ACT + col] = x0[(g * BT + b) * 256 + col];
    }
    for (int idx = t; idx < BT * 64; idx += THREADS) {
        int b = idx >> 6, j = idx & 63;
        sAct[b * S_ACT + 256 + j] = dseq[(size_t)(g * BT + b) * (NSTEPS * 64) + j];
    }

    // ---- work decomposition ----
    const int lane = t & 31, warp = t >> 5;
    // w-phase: warp = chunk (20 x K=16), lane = 4r x 4b tile
    const int row0w = (lane & 7) * 4, b0w = lane >> 3;
    const int j0w = warp * 16;
    // xe-phase: 16 chunks x 40 tiles; part-A K=20 over [0,320), part-B K=16 over w
    const int tl = t % 40, cx = t / 40;
    const int b0x = tl / 10, row0x = (tl % 10) * 4;
    const int j0A = cx * 20;
    const int j0B = 320 + cx * 16;
    // reductions
    const int rb = t >> 5, rr = t & 31;          // w (t<512)
    const int xb = t / 40, xr = t % 40;          // xe (all 640)

    float* gw = g_wbuf + g * (BT * 256);
    float* gx = g_xbuf + g * (BT * 256);
    const float4* gw4 = reinterpret_cast<const float4*>(gw);
    const float4* gx4 = reinterpret_cast<const float4*>(gx);

    float dpre0 = 0.f, dpre1 = 0.f;
    const int d0b = t >> 6, d0j = t & 63;        // idx t (<640)
    const int i1 = t + THREADS;                  // idx t+640 (<1024 -> t<384)
    const int d1b = i1 >> 6, d1j = i1 & 63;

    __syncthreads();

    for (int k = 0; k < NSTEPS; ++k) {
        // ---- w-phase mm: 32 rows, K=320 ----
        {
            ull a01[4] = {0, 0, 0, 0}, a23[4] = {0, 0, 0, 0};
            mmT<4, 32>(sW1T + j0w * 32 + row0w, sAct + b0w * S_ACT + j0w, a01, a23);
            float* P = sPar + warp * PARW + b0w * PS_W + row0w;
#pragma unroll
            for (int kk = 0; kk < 4; kk++)
                *reinterpret_cast<ulonglong2*>(P + kk * (4 * PS_W)) =
                    make_ulonglong2(a01[kk], a23[kk]);
        }
        __syncthreads();
        if (t < 512) {
            float s = 0.f;
#pragma unroll
            for (int c = 0; c < 20; c++) s += sPar[c * PARW + rb * PS_W + rr];
            __stcg(&gw[rb * 256 + rw + rr], tanhf(s));
        }
        cluster_arrive();   // release w; window below overlaps peers' arrival

        // ---- overlap window: xe part-A (x|d region) + d_{k+1} prefetch ----
        ull x01[4] = {0, 0, 0, 0}, x23[4] = {0, 0, 0, 0};
        mmT<5, 40>(sW2T + j0A * 40 + row0x, sAct + b0x * S_ACT + j0A, x01, x23);
        {
            int kp = (k + 1 < NSTEPS) ? (k + 1) : (NSTEPS - 1);
            dpre0 = dseq[(size_t)(g * BT + d0b) * (NSTEPS * 64) + (size_t)kp * 64 + d0j];
            if (i1 < 1024)
                dpre1 = dseq[(size_t)(g * BT + d1b) * (NSTEPS * 64) + (size_t)kp * 64 + d1j];
        }
        cluster_wait();
        // gather full w: 1024 float4 = 512 threads x 2
        if (t < 512) {
            int idx = t;
            float4 v = __ldcg(gw4 + idx);
            *reinterpret_cast<float4*>(&sAct[(idx >> 6) * S_ACT + 320 + (idx & 63) * 4]) = v;
            idx = t + 512;
            v = __ldcg(gw4 + idx);
            *reinterpret_cast<float4*>(&sAct[(idx >> 6) * S_ACT + 320 + (idx & 63) * 4]) = v;
        }
        __syncthreads();

        // ---- xe part-B (w region), then store partials ----
        mmT<4, 40>(sW2T + j0B * 40 + row0x, sAct + b0x * S_ACT + j0B, x01, x23);
        {
            float* P = sPar + cx * PARX + b0x * PS_X + row0x;
#pragma unroll
            for (int kk = 0; kk < 4; kk++)
                *reinterpret_cast<ulonglong2*>(P + kk * (4 * PS_X)) =
                    make_ulonglong2(x01[kk], x23[kk]);
        }
        __syncthreads();
        float xres = 0.f;
#pragma unroll
        for (int c = 0; c < 16; c++) xres += sPar[c * PARX + xb * PS_X + xr];
        if (xr < 32) __stcg(&gx[xb * 256 + rw + xr], xres);
        cluster_arrive();   // release x; window overlaps e-store + d-commit

        if (xr >= 32)
            out[(size_t)(g * BT + xb) * (NSTEPS * 64) + (size_t)k * 64 + re + (xr - 32)] = xres;
        sAct[d0b * S_ACT + 256 + d0j] = dpre0;
        if (i1 < 1024) sAct[d1b * S_ACT + 256 + d1j] = dpre1;

        cluster_wait();
        // gather full x_new: 1024 float4 = 512 threads x 2
        if (t < 512) {
            int idx = t;
            float4 v = __ldcg(gx4 + idx);
            *reinterpret_cast<float4*>(&sAct[(idx >> 6) * S_ACT + (idx & 63) * 4]) = v;
            idx = t + 512;
            v = __ldcg(gx4 + idx);
            *reinterpret_cast<float4*>(&sAct[(idx >> 6) * S_ACT + (idx & 63) * 4]) = v;
        }
        __syncthreads();
    }

    // final states: x_final (act x-part), w_{N-1} (act w-part)
    if (t < 512) {
        int b = t >> 5, row = t & 31;
        size_t gb = (size_t)(g * BT + b);
        out[BASE_X + gb * 256 + rw + row] = sAct[b * S_ACT + rw + row];
        out[BASE_W + gb * 256 + rw + row] = sAct[b * S_ACT + 320 + rw + row];
    }
}

extern "C" void kernel_launch(void* const* d_in, const int* in_sizes, int n_in,
                              void* d_out, int out_size) {
    (void)in_sizes; (void)n_in; (void)out_size;
    const float* dseq = (const float*)d_in[0];
    const float* x0   = (const float*)d_in[1];
    const float* A    = (const float*)d_in[2];
    const float* B    = (const float*)d_in[3];
    const float* B2   = (const float*)d_in[4];
    const float* C    = (const float*)d_in[5];
    const float* D    = (const float*)d_in[6];
    const float* D12  = (const float*)d_in[7];
    const float* C2   = (const float*)d_in[8];
    const float* D21  = (const float*)d_in[9];
    float* out = (float*)d_out;

    fuse_kernel<<<64, 256>>>(A, B, B2, C, D, D12);

    const size_t smem_bytes = (size_t)SMEM_FLOATS * sizeof(float);
    cudaFuncSetAttribute(lure_kernel, cudaFuncAttributeMaxDynamicSharedMemorySize,
                         (int)smem_bytes);
    lure_kernel<<<GROUPS * RANKS, THREADS, smem_bytes>>>(dseq, x0, A, B, B2,
                                                         C2, D21, out);
}